// round 15
// baseline (speedup 1.0000x reference)
#include <cuda_runtime.h>
#include <cuda_fp16.h>
#include <cstdint>
#include <math.h>

#define NN    32
#define BSZv  512
#define NE    7
#define DIN   512
#define DHv   256
#define RHv   64
#define NPAIR 21
#define M_ROWS (NN * BSZv * NE)   // 114688
#define NCFG  128
#define NTILES 896
#define PGRID  152

// ---------------- scratch ------------------------------------------------------
__device__ __align__(128) __half g_w0p[(size_t)(DIN / 32) * DHv * 32];
__device__ __align__(128) __half g_w1p[(size_t)(DHv / 32) * DHv * 32];
__device__ __align__(128) __half g_h1p[(size_t)(DHv / 32) * M_ROWS * 32];
__device__ float g_un[(size_t)M_ROWS * 2];
__device__ float g_pairsum[(size_t)BSZv * NCFG];

// ---------------- PTX helpers ---------------------------------------------------
__device__ __forceinline__ uint32_t smem_u32(const void* p) {
    uint32_t a;
    asm("{ .reg .u64 t; cvta.to.shared.u64 t, %1; cvt.u32.u64 %0, t; }" : "=r"(a) : "l"(p));
    return a;
}
__device__ __forceinline__ void ldsm4(uint32_t a, uint32_t* r) {
    asm volatile("ldmatrix.sync.aligned.m8n8.x4.shared.b16 {%0,%1,%2,%3}, [%4];"
                 : "=r"(r[0]), "=r"(r[1]), "=r"(r[2]), "=r"(r[3]) : "r"(a));
}
// fp16-accumulate MMA: D,C are 2 regs (4 fp16)
__device__ __forceinline__ void mma_h(uint32_t* d, const uint32_t* a,
                                      uint32_t b0, uint32_t b1,
                                      uint32_t c0, uint32_t c1) {
    asm volatile("mma.sync.aligned.m16n8k16.row.col.f16.f16.f16.f16 "
                 "{%0,%1}, {%2,%3,%4,%5}, {%6,%7}, {%8,%9};"
                 : "=r"(d[0]), "=r"(d[1])
                 : "r"(a[0]), "r"(a[1]), "r"(a[2]), "r"(a[3]),
                   "r"(b0), "r"(b1), "r"(c0), "r"(c1));
}
#define CP16(dst, src) asm volatile("cp.async.cg.shared.global [%0], [%1], 16;" :: "r"(dst), "l"(src))
#define CPCOMMIT()     asm volatile("cp.async.commit_group;" ::: "memory")
#define CPWAIT2()      asm volatile("cp.async.wait_group 2;" ::: "memory")
#define STS128(a, v0, v1, v2, v3) \
    asm volatile("st.shared.v4.b32 [%0], {%1,%2,%3,%4};" :: "r"(a), "r"(v0), "r"(v1), "r"(v2), "r"(v3))

__device__ __forceinline__ uint32_t packf2(float lo, float hi) {
    uint32_t d;
    asm("cvt.rn.f16x2.f32 %0, %1, %2;" : "=r"(d) : "f"(hi), "f"(lo));
    return d;
}
__device__ __forceinline__ float2 h2f2(uint32_t h) {
    __half2 t = *reinterpret_cast<__half2*>(&h);
    return __half22float2(t);
}

// ---------------- weight packing (BK32 rows) ------------------------------------
__global__ __launch_bounds__(256) void pack_weights(
    const float* __restrict__ W, __half* __restrict__ dst, int K)
{
    int idx = blockIdx.x * 256 + threadIdx.x;
    if (idx >= K * 256) return;
    int k = idx >> 8, n = idx & 255;
    size_t o = ((size_t)(k >> 5) * 256 + n) * 32 + (k & 31);
    dst[o] = __float2half_rn(W[idx]);
}

// ---------------- GEMM: 128x256 CTA, 64x64 warp tile, fp16-acc + promotion ------
#define RES_SZ   131072u
#define A_OFF    131072u
#define BS_OFF   163840u
#define SMEM_SZ0 230400
#define SMEM_SZ1 166912

template <int KDIM, int MODE>
__global__ __launch_bounds__(256, 1) void gemm_tc(
    const float* __restrict__ Af, const __half* __restrict__ Ap,
    const __half* __restrict__ Wp, const float* __restrict__ bias,
    const float* __restrict__ W2, __half* __restrict__ outp,
    float* __restrict__ un)
{
    extern __shared__ char smem[];
    constexpr int NC = KDIM / 32;
    constexpr int RES_CH = 8;
    constexpr uint32_t SM_BIAS = (MODE == 0) ? 229376u : 163840u;
    constexpr uint32_t SM_W2v  = 164864u;
    const int tid = threadIdx.x;
    const int lane = tid & 31;
    const int wid = tid >> 5;
    const int warp_m = wid >> 2, warp_n = wid & 3;
    const int bid = blockIdx.x;
    const int GRID = gridDim.x;

    const uint32_t sb = smem_u32(smem);
    float* biasS = (float*)(smem + SM_BIAS);
    float* W2s = (float*)(smem + SM_W2v);
    biasS[tid] = bias[tid];
    if (MODE == 1) { W2s[tid] = W2[tid]; W2s[tid + 256] = W2[tid + 256]; }

    const int crow = tid >> 1;
    const int chalf = tid & 1;
    const int cxor = crow & 7;

    const uint32_t aRowOff = (uint32_t)(warp_m * 64 + (lane & 15)) * 128;
    const uint32_t aKsel = (uint32_t)(lane >> 4);
    const uint32_t bRowOff = (uint32_t)(warp_n * 64 + ((lane >> 4) << 3) + (lane & 7)) * 128;
    const uint32_t bKsel = (uint32_t)((lane >> 3) & 1);
    const uint32_t xr = (uint32_t)(lane & 7);

    const int myTiles = (NTILES - bid + GRID - 1) / GRID;
    const int total = myTiles * NC;

    float acc[4][8][4];
#pragma unroll
    for (int a = 0; a < 4; a++)
#pragma unroll
        for (int b = 0; b < 8; b++)
#pragma unroll
            for (int q = 0; q < 4; q++) acc[a][b][q] = 0.f;

    float rA[16];

    // ---- resident B ----
    {
        const int row = tid;
        const uint32_t rx = (uint32_t)(row & 7);
#pragma unroll
        for (int p = 0; p < RES_CH / 2; p++) {
#pragma unroll
            for (int e = 0; e < 2; e++) {
                const char* src = (const char*)(Wp + ((size_t)(2 * p + e) * 256 + row) * 32);
                uint32_t dst = sb + (uint32_t)p * 32768 + (uint32_t)row * 128;
#pragma unroll
                for (int j = 0; j < 4; j++)
                    CP16(dst + (((uint32_t)(4 * e + j)) ^ rx) * 16, src + j * 16);
            }
        }
        CPCOMMIT();
    }

    auto loadA_regs = [&](int s) {
        int i = s / NC, c = s % NC;
        int t = bid + i * GRID;
        size_t mB = (size_t)t * 128;
        const float* p = Af + (mB + crow) * KDIM + c * 32 + chalf * 16;
        *(float4*)(rA)      = *(const float4*)(p);
        *(float4*)(rA + 4)  = *(const float4*)(p + 4);
        *(float4*)(rA + 8)  = *(const float4*)(p + 8);
        *(float4*)(rA + 12) = *(const float4*)(p + 12);
    };
    auto storeA_regs = [&](uint32_t q) {
        uint32_t dst = sb + A_OFF + (q >> 1) * 16384 + crow * 128;
        uint32_t gb = 4u * (q & 1);
        uint32_t hh[8];
#pragma unroll
        for (int k = 0; k < 8; k++)
            hh[k] = packf2(rA[2 * k], rA[2 * k + 1]);
        STS128(dst + ((gb + 2 * chalf + 0) ^ cxor) * 16, hh[0], hh[1], hh[2], hh[3]);
        STS128(dst + ((gb + 2 * chalf + 1) ^ cxor) * 16, hh[4], hh[5], hh[6], hh[7]);
    };
    auto prefetch = [&](int ss) {
        if (ss < total) {
            int c = ss % NC;
            uint32_t q = (uint32_t)ss & 3;
            uint32_t gb = 4u * (q & 1);
            if (MODE == 1) {
                int i = ss / NC;
                int t = bid + i * GRID;
                size_t mB = (size_t)t * 128;
                const char* srcA = (const char*)(Ap + ((size_t)c * M_ROWS + mB + crow) * 32 + chalf * 16);
                uint32_t dstA = sb + A_OFF + (q >> 1) * 16384 + crow * 128;
#pragma unroll
                for (int j = 0; j < 2; j++)
                    CP16(dstA + ((gb + 2 * chalf + j) ^ cxor) * 16, srcA + j * 16);
            } else if (c >= RES_CH) {
                const int row = tid;
                const uint32_t rx = (uint32_t)(row & 7);
                const char* srcB = (const char*)(Wp + ((size_t)c * 256 + row) * 32);
                uint32_t dstB = sb + BS_OFF + (q >> 1) * 32768 + (uint32_t)row * 128;
#pragma unroll
                for (int j = 0; j < 4; j++)
                    CP16(dstB + ((gb + (uint32_t)j) ^ rx) * 16, srcB + j * 16);
            }
        }
        CPCOMMIT();
    };
    auto compute = [&](int sidx) {
        int c = sidx % NC;
        uint32_t q = (uint32_t)sidx & 3;
        uint32_t ga = 4u * (q & 1);
        uint32_t Ab = sb + A_OFF + (q >> 1) * 16384 + aRowOff;
        uint32_t Bb, gb;
        if (MODE == 0 && c >= RES_CH) {
            Bb = sb + BS_OFF + (q >> 1) * 32768 + bRowOff;
            gb = ga;
        } else {
            Bb = sb + (uint32_t)(c >> 1) * 32768 + bRowOff;
            gb = 4u * (uint32_t)(c & 1);
        }
        // hoist B fragments for both k-steps (32 regs)
        uint32_t bF[2][16];
#pragma unroll
        for (int ks = 0; ks < 2; ks++)
#pragma unroll
            for (int nb = 0; nb < 4; nb++)
                ldsm4(Bb + (uint32_t)nb * 2048 + ((gb + 2 * ks + bKsel) ^ xr) * 16,
                      bF[ks] + 4 * nb);
        const uint32_t z = 0u;
#pragma unroll
        for (int mi = 0; mi < 4; mi++) {
            uint32_t ah0[4], ah1[4];
            ldsm4(Ab + mi * 2048 + ((ga + 0 + aKsel) ^ xr) * 16, ah0);
            ldsm4(Ab + mi * 2048 + ((ga + 2 + aKsel) ^ xr) * 16, ah1);
            uint32_t hacc[8][2];
#pragma unroll
            for (int nj = 0; nj < 8; nj++)
                mma_h(hacc[nj], ah0, bF[0][2 * nj], bF[0][2 * nj + 1], z, z);
#pragma unroll
            for (int nj = 0; nj < 8; nj++)
                mma_h(hacc[nj], ah1, bF[1][2 * nj], bF[1][2 * nj + 1],
                      hacc[nj][0], hacc[nj][1]);
#pragma unroll
            for (int nj = 0; nj < 8; nj++) {
                float2 p0 = h2f2(hacc[nj][0]);
                float2 p1 = h2f2(hacc[nj][1]);
                acc[mi][nj][0] += p0.x;
                acc[mi][nj][1] += p0.y;
                acc[mi][nj][2] += p1.x;
                acc[mi][nj][3] += p1.y;
            }
        }
    };

    const int rloc = warp_m * 64 + (lane >> 2);
    const int nl0 = warp_n * 64 + (lane & 3) * 2;

    // ---- prologue ----
    prefetch(0);
    prefetch(1);
    if (MODE == 0) {
        loadA_regs(0); storeA_regs(0);
        if (total > 1) { loadA_regs(1); storeA_regs(1); }
        if (total > 2) loadA_regs(2);
    }

    // ---- main loop ----
    for (int s = 0; s < total; s++) {
        prefetch(s + 2);
        CPWAIT2();
        __syncthreads();
        compute(s);

        if ((s % NC) == NC - 1) {
            const int t = bid + (s / NC) * GRID;
            const size_t mBase = (size_t)t * 128;
            if (MODE == 0) {
#pragma unroll
                for (int mi = 0; mi < 4; mi++)
#pragma unroll
                    for (int nj = 0; nj < 8; nj++) {
                        int nl = nl0 + nj * 8;
                        float b0v = biasS[nl], b1v = biasS[nl + 1];
                        float v00 = fmaxf(acc[mi][nj][0] + b0v, 0.f);
                        float v01 = fmaxf(acc[mi][nj][1] + b1v, 0.f);
                        float v10 = fmaxf(acc[mi][nj][2] + b0v, 0.f);
                        float v11 = fmaxf(acc[mi][nj][3] + b1v, 0.f);
                        int cpk = nl >> 5, slot = nl & 31;
                        size_t r0 = mBase + rloc + mi * 16;
                        size_t o0 = ((size_t)cpk * M_ROWS + r0) * 32 + slot;
                        size_t o1 = o0 + 8 * 32;
                        *(uint32_t*)(outp + o0) = packf2(v00, v01);
                        *(uint32_t*)(outp + o1) = packf2(v10, v11);
                        acc[mi][nj][0] = 0.f; acc[mi][nj][1] = 0.f;
                        acc[mi][nj][2] = 0.f; acc[mi][nj][3] = 0.f;
                    }
            } else {
                float up[16];
#pragma unroll
                for (int i = 0; i < 16; i++) up[i] = 0.f;
#pragma unroll
                for (int mi = 0; mi < 4; mi++)
#pragma unroll
                    for (int nj = 0; nj < 8; nj++) {
                        int nl = nl0 + nj * 8;
                        float b0v = biasS[nl], b1v = biasS[nl + 1];
                        float w00 = W2s[2 * nl],     w01 = W2s[2 * nl + 1];
                        float w10 = W2s[2 * nl + 2], w11 = W2s[2 * nl + 3];
                        float v00 = fmaxf(acc[mi][nj][0] + b0v, 0.f);
                        float v01 = fmaxf(acc[mi][nj][1] + b1v, 0.f);
                        float v10 = fmaxf(acc[mi][nj][2] + b0v, 0.f);
                        float v11 = fmaxf(acc[mi][nj][3] + b1v, 0.f);
                        up[mi * 4 + 0] += v00 * w00 + v01 * w10;
                        up[mi * 4 + 1] += v00 * w01 + v01 * w11;
                        up[mi * 4 + 2] += v10 * w00 + v11 * w10;
                        up[mi * 4 + 3] += v10 * w01 + v11 * w11;
                        acc[mi][nj][0] = 0.f; acc[mi][nj][1] = 0.f;
                        acc[mi][nj][2] = 0.f; acc[mi][nj][3] = 0.f;
                    }
#pragma unroll
                for (int k = 1; k <= 2; k <<= 1)
#pragma unroll
                    for (int i = 0; i < 16; i++)
                        up[i] += __shfl_xor_sync(0xffffffffu, up[i], k);
                if ((lane & 3) == 0) {
#pragma unroll
                    for (int mi = 0; mi < 4; mi++) {
                        size_t r0 = mBase + rloc + mi * 16;
                        size_t r1 = r0 + 8;
                        atomicAdd(&un[r0 * 2 + 0], up[mi * 4 + 0]);
                        atomicAdd(&un[r0 * 2 + 1], up[mi * 4 + 1]);
                        atomicAdd(&un[r1 * 2 + 0], up[mi * 4 + 2]);
                        atomicAdd(&un[r1 * 2 + 1], up[mi * 4 + 3]);
                    }
                }
            }
        }

        if (MODE == 0) {
            if (s + 2 < total) {
                storeA_regs((uint32_t)(s + 2) & 3);
                if (s + 3 < total) loadA_regs(s + 3);
            }
        }
    }
}

// -------- binary MLP + pairwise config sums ----------------------------------
__global__ __launch_bounds__(128) void binary_kernel(
    const float* __restrict__ ctx, const float* __restrict__ R0,
    const float* __restrict__ r0, const float* __restrict__ R1,
    const float* __restrict__ r1, float* __restrict__ pairsum)
{
    __shared__ float cd[NPAIR][5];
    __shared__ float R0s[5][RHv];
    __shared__ float r0s[RHv];
    __shared__ float R1s[RHv][3];
    __shared__ float r1s[3];
    __shared__ float h2s[NPAIR][RHv];
    __shared__ float bp4s[NPAIR][4];

    int b = blockIdx.x, t = threadIdx.x;
    for (int i = t; i < NPAIR * 5; i += 128) cd[i / 5][i % 5] = ctx[b * NPAIR * 5 + i];
    for (int i = t; i < 5 * RHv; i += 128) R0s[i / RHv][i % RHv] = R0[i];
    if (t < RHv) r0s[t] = r0[t];
    for (int i = t; i < RHv * 3; i += 128) R1s[i / 3][i % 3] = R1[i];
    if (t < 3) r1s[t] = r1[t];
    __syncthreads();

    for (int idx = t; idx < NPAIR * RHv; idx += 128) {
        int p = idx / RHv, u = idx % RHv;
        float v = r0s[u];
#pragma unroll
        for (int x = 0; x < 5; x++) v += cd[p][x] * R0s[x][u];
        h2s[p][u] = fmaxf(v, 0.f);
    }
    __syncthreads();

    if (t < NPAIR * 3) {
        int p = t / 3, y = t % 3;
        float v = r1s[y];
#pragma unroll
        for (int u = 0; u < RHv; u++) v += h2s[p][u] * R1s[u][y];
        if (y == 0) bp4s[p][0] = v;
        else if (y == 1) { bp4s[p][1] = v; bp4s[p][2] = v; }
        else bp4s[p][3] = v;
    }
    __syncthreads();

    int s = t;
    float accv = 0.f;
    int p = 0;
#pragma unroll
    for (int i = 0; i < NE; i++)
#pragma unroll
        for (int j = i + 1; j < NE; j++) {
            int bi = (s >> (6 - i)) & 1;
            int bj = (s >> (6 - j)) & 1;
            accv += bp4s[p][bi * 2 + bj];
            p++;
        }
    pairsum[(size_t)b * NCFG + s] = accv;
}

// ---------------- joint + lse + marginals -------------------------------------
__global__ __launch_bounds__(256) void joint_kernel(
    const float* __restrict__ un, const float* __restrict__ ps,
    const float* __restrict__ b2v, float* __restrict__ out_marg,
    float* __restrict__ out_joint)
{
    int w = blockIdx.x * 8 + (threadIdx.x >> 5);
    int lane = threadIdx.x & 31;
    int b = w & (BSZv - 1), n = w >> 9;
    size_t nb = (size_t)n * BSZv + b;

    float val = 0.f;
    if (lane < 14) val = un[nb * 14 + lane] + b2v[lane & 1];
    float u[14];
#pragma unroll
    for (int i = 0; i < 14; i++) u[i] = __shfl_sync(0xffffffffu, val, i);

    float j[4], e[4];
    float mx = -1e30f;
#pragma unroll
    for (int q = 0; q < 4; q++) {
        int s = q * 32 + lane;
        float t = ps[(size_t)b * NCFG + s];
#pragma unroll
        for (int i = 0; i < NE; i++) t += u[i * 2 + ((s >> (6 - i)) & 1)];
        j[q] = t;
        mx = fmaxf(mx, t);
    }
#pragma unroll
    for (int o = 16; o; o >>= 1) mx = fmaxf(mx, __shfl_xor_sync(0xffffffffu, mx, o));

    float p1[NE], p0[NE];
#pragma unroll
    for (int i = 0; i < NE; i++) { p1[i] = 0.f; p0[i] = 0.f; }
#pragma unroll
    for (int q = 0; q < 4; q++) {
        int s = q * 32 + lane;
        e[q] = __expf(j[q] - mx);
#pragma unroll
        for (int i = 0; i < NE; i++) {
            if ((s >> (6 - i)) & 1) p1[i] += e[q];
            else p0[i] += e[q];
        }
    }
#pragma unroll
    for (int o = 16; o; o >>= 1)
#pragma unroll
        for (int i = 0; i < NE; i++) {
            p1[i] += __shfl_xor_sync(0xffffffffu, p1[i], o);
            p0[i] += __shfl_xor_sync(0xffffffffu, p0[i], o);
        }

    float lt = __logf(p1[0] + p0[0]);
#pragma unroll
    for (int q = 0; q < 4; q++)
        out_joint[nb * NCFG + q * 32 + lane] = j[q] - mx - lt;
    if (lane < NE)
        out_marg[nb * NE + lane] = __logf(p1[lane]) - __logf(p0[lane]);
}

// ---------------- launch -------------------------------------------------------
extern "C" void kernel_launch(void* const* d_in, const int* in_sizes, int n_in,
                              void* d_out, int out_size)
{
    const float* input = (const float*)d_in[0];
    const float* ctx   = (const float*)d_in[1];
    const float* W0 = (const float*)d_in[4];
    const float* b0 = (const float*)d_in[5];
    const float* W1 = (const float*)d_in[6];
    const float* b1 = (const float*)d_in[7];
    const float* W2 = (const float*)d_in[8];
    const float* b2 = (const float*)d_in[9];
    const float* R0 = (const float*)d_in[10];
    const float* r0 = (const float*)d_in[11];
    const float* R1 = (const float*)d_in[12];
    const float* r1 = (const float*)d_in[13];

    float* out = (float*)d_out;
    float* out_marg = out;
    float* out_joint = out + (size_t)M_ROWS;

    __half *w0p, *w1p, *h1p;
    float *un, *psum;
    cudaGetSymbolAddress((void**)&w0p, g_w0p);
    cudaGetSymbolAddress((void**)&w1p, g_w1p);
    cudaGetSymbolAddress((void**)&h1p, g_h1p);
    cudaGetSymbolAddress((void**)&un, g_un);
    cudaGetSymbolAddress((void**)&psum, g_pairsum);

    cudaFuncSetAttribute(gemm_tc<DIN, 0>, cudaFuncAttributeMaxDynamicSharedMemorySize, SMEM_SZ0);
    cudaFuncSetAttribute(gemm_tc<DHv, 1>, cudaFuncAttributeMaxDynamicSharedMemorySize, SMEM_SZ1);

    pack_weights<<<DIN, 256>>>(W0, w0p, DIN);
    pack_weights<<<DHv, 256>>>(W1, w1p, DHv);
    cudaMemsetAsync(un, 0, (size_t)M_ROWS * 2 * sizeof(float));

    gemm_tc<DIN, 0><<<PGRID, 256, SMEM_SZ0>>>(
        input, nullptr, w0p, b0, nullptr, h1p, nullptr);
    gemm_tc<DHv, 1><<<PGRID, 256, SMEM_SZ1>>>(
        nullptr, h1p, w1p, b1, W2, nullptr, un);
    binary_kernel<<<BSZv, 128>>>(ctx, R0, r0, R1, r1, psum);
    joint_kernel<<<(NN * BSZv) / 8, 256>>>(un, psum, b2, out_marg, out_joint);
}

// round 16
// speedup vs baseline: 1.2426x; 1.2426x over previous
#include <cuda_runtime.h>
#include <cuda_fp16.h>
#include <cstdint>
#include <math.h>

#define NN    32
#define BSZv  512
#define NE    7
#define DIN   512
#define DHv   256
#define RHv   64
#define NPAIR 21
#define M_ROWS (NN * BSZv * NE)   // 114688
#define NCFG  128
#define NTILES 896
#define PGRID  152

// ---------------- scratch ------------------------------------------------------
__device__ __align__(128) __half g_w0p[(size_t)(DIN / 32) * DHv * 32];
__device__ __align__(128) __half g_w1p[(size_t)(DHv / 32) * DHv * 32];
__device__ __align__(128) __half g_h1p[(size_t)(DHv / 32) * M_ROWS * 32];
__device__ float g_un[(size_t)M_ROWS * 2];
__device__ float g_pairsum[(size_t)BSZv * NCFG];

// ---------------- PTX helpers ---------------------------------------------------
__device__ __forceinline__ uint32_t smem_u32(const void* p) {
    uint32_t a;
    asm("{ .reg .u64 t; cvta.to.shared.u64 t, %1; cvt.u32.u64 %0, t; }" : "=r"(a) : "l"(p));
    return a;
}
__device__ __forceinline__ void ldsm4(uint32_t a, uint32_t* r) {
    asm volatile("ldmatrix.sync.aligned.m8n8.x4.shared.b16 {%0,%1,%2,%3}, [%4];"
                 : "=r"(r[0]), "=r"(r[1]), "=r"(r[2]), "=r"(r[3]) : "r"(a));
}
__device__ __forceinline__ void mma_f16(float* c, const uint32_t* a, uint32_t b0, uint32_t b1) {
    asm volatile("mma.sync.aligned.m16n8k16.row.col.f32.f16.f16.f32 "
                 "{%0,%1,%2,%3}, {%4,%5,%6,%7}, {%8,%9}, {%0,%1,%2,%3};"
                 : "+f"(c[0]), "+f"(c[1]), "+f"(c[2]), "+f"(c[3])
                 : "r"(a[0]), "r"(a[1]), "r"(a[2]), "r"(a[3]), "r"(b0), "r"(b1));
}
#define CP16(dst, src) asm volatile("cp.async.cg.shared.global [%0], [%1], 16;" :: "r"(dst), "l"(src))
#define CPCOMMIT()     asm volatile("cp.async.commit_group;" ::: "memory")
#define CPWAIT2()      asm volatile("cp.async.wait_group 2;" ::: "memory")
#define STS128(a, v0, v1, v2, v3) \
    asm volatile("st.shared.v4.b32 [%0], {%1,%2,%3,%4};" :: "r"(a), "r"(v0), "r"(v1), "r"(v2), "r"(v3))

__device__ __forceinline__ uint32_t packf2(float lo, float hi) {
    uint32_t d;
    asm("cvt.rn.f16x2.f32 %0, %1, %2;" : "=r"(d) : "f"(hi), "f"(lo));
    return d;
}

// ---------------- prep: binary MLP + pairsum, W0 pack, W1 pack (one launch) -----
__global__ __launch_bounds__(128) void prep_kernel(
    const float* __restrict__ ctx, const float* __restrict__ R0,
    const float* __restrict__ r0, const float* __restrict__ R1,
    const float* __restrict__ r1, float* __restrict__ pairsum,
    const float* __restrict__ W0, __half* __restrict__ w0p,
    const float* __restrict__ W1, __half* __restrict__ w1p)
{
    __shared__ float cd[NPAIR][5];
    __shared__ float R0s[5][RHv];
    __shared__ float r0s[RHv];
    __shared__ float R1s[RHv][3];
    __shared__ float r1s[3];
    __shared__ float h2s[NPAIR][RHv];
    __shared__ float bp4s[NPAIR][4];

    const int blk = blockIdx.x;
    const int t = threadIdx.x;

    if (blk >= 512) {
        // weight packing, 128 threads/block
        if (blk < 1536) {
            int idx = (blk - 512) * 128 + t;        // W0: 512*256 elems
            int k = idx >> 8, n = idx & 255;
            size_t o = ((size_t)(k >> 5) * 256 + n) * 32 + (k & 31);
            w0p[o] = __float2half_rn(W0[idx]);
        } else {
            int idx = (blk - 1536) * 128 + t;       // W1: 256*256 elems
            int k = idx >> 8, n = idx & 255;
            size_t o = ((size_t)(k >> 5) * 256 + n) * 32 + (k & 31);
            w1p[o] = __float2half_rn(W1[idx]);
        }
        return;
    }

    // ---- binary MLP + pairwise config sums for batch b = blk ----
    const int b = blk;
    for (int i = t; i < NPAIR * 5; i += 128) cd[i / 5][i % 5] = ctx[b * NPAIR * 5 + i];
    for (int i = t; i < 5 * RHv; i += 128) R0s[i / RHv][i % RHv] = R0[i];
    if (t < RHv) r0s[t] = r0[t];
    for (int i = t; i < RHv * 3; i += 128) R1s[i / 3][i % 3] = R1[i];
    if (t < 3) r1s[t] = r1[t];
    __syncthreads();

    for (int idx = t; idx < NPAIR * RHv; idx += 128) {
        int p = idx / RHv, u = idx % RHv;
        float v = r0s[u];
#pragma unroll
        for (int x = 0; x < 5; x++) v += cd[p][x] * R0s[x][u];
        h2s[p][u] = fmaxf(v, 0.f);
    }
    __syncthreads();

    if (t < NPAIR * 3) {
        int p = t / 3, y = t % 3;
        float v = r1s[y];
#pragma unroll
        for (int u = 0; u < RHv; u++) v += h2s[p][u] * R1s[u][y];
        if (y == 0) bp4s[p][0] = v;
        else if (y == 1) { bp4s[p][1] = v; bp4s[p][2] = v; }
        else bp4s[p][3] = v;
    }
    __syncthreads();

    int s = t;
    float accv = 0.f;
    int p = 0;
#pragma unroll
    for (int i = 0; i < NE; i++)
#pragma unroll
        for (int j = i + 1; j < NE; j++) {
            int bi = (s >> (6 - i)) & 1;
            int bj = (s >> (6 - j)) & 1;
            accv += bp4s[p][bi * 2 + bj];
            p++;
        }
    pairsum[(size_t)b * NCFG + s] = accv;
}

// ---------------- GEMM: 128x256 CTA tile, 64x64 warp tile, 1 CTA/SM ------------
#define RES_SZ   131072u
#define A_OFF    131072u
#define BS_OFF   163840u
// MODE0: bias @ 229376 (1KB)  -> total 230400
// MODE1: bias @ 163840 (1KB), W2 @ 164864 (2KB), un-scratch @ 166912 (3KB) -> 169984
#define UN_SC    166912u
#define SMEM_SZ0 230400
#define SMEM_SZ1 169984

template <int KDIM, int MODE>
__global__ __launch_bounds__(256, 1) void gemm_tc(
    const float* __restrict__ Af, const __half* __restrict__ Ap,
    const __half* __restrict__ Wp, const float* __restrict__ bias,
    const float* __restrict__ W2, __half* __restrict__ outp,
    float* __restrict__ un)
{
    extern __shared__ char smem[];
    constexpr int NC = KDIM / 32;
    constexpr int RES_CH = 8;
    constexpr uint32_t SM_BIAS = (MODE == 0) ? 229376u : 163840u;
    constexpr uint32_t SM_W2v  = 164864u;
    const int tid = threadIdx.x;
    const int lane = tid & 31;
    const int wid = tid >> 5;
    const int warp_m = wid >> 2, warp_n = wid & 3;
    const int bid = blockIdx.x;
    const int GRID = gridDim.x;

    const uint32_t sb = smem_u32(smem);
    float* biasS = (float*)(smem + SM_BIAS);
    float* W2s = (float*)(smem + SM_W2v);
    biasS[tid] = bias[tid];
    if (MODE == 1) { W2s[tid] = W2[tid]; W2s[tid + 256] = W2[tid + 256]; }

    const int crow = tid >> 1;
    const int chalf = tid & 1;
    const int cxor = crow & 7;

    const uint32_t aRowOff = (uint32_t)(warp_m * 64 + (lane & 15)) * 128;
    const uint32_t aKsel = (uint32_t)(lane >> 4);
    const uint32_t bRowOff = (uint32_t)(warp_n * 64 + ((lane >> 4) << 3) + (lane & 7)) * 128;
    const uint32_t bKsel = (uint32_t)((lane >> 3) & 1);
    const uint32_t xr = (uint32_t)(lane & 7);

    const int myTiles = (NTILES - bid + GRID - 1) / GRID;
    const int total = myTiles * NC;

    float acc[4][8][4];
#pragma unroll
    for (int a = 0; a < 4; a++)
#pragma unroll
        for (int b = 0; b < 8; b++)
#pragma unroll
            for (int q = 0; q < 4; q++) acc[a][b][q] = 0.f;

    float rA[16];

    // ---- resident B ----
    {
        const int row = tid;
        const uint32_t rx = (uint32_t)(row & 7);
#pragma unroll
        for (int p = 0; p < RES_CH / 2; p++) {
#pragma unroll
            for (int e = 0; e < 2; e++) {
                const char* src = (const char*)(Wp + ((size_t)(2 * p + e) * 256 + row) * 32);
                uint32_t dst = sb + (uint32_t)p * 32768 + (uint32_t)row * 128;
#pragma unroll
                for (int j = 0; j < 4; j++)
                    CP16(dst + (((uint32_t)(4 * e + j)) ^ rx) * 16, src + j * 16);
            }
        }
        CPCOMMIT();
    }

    auto loadA_regs = [&](int s) {
        int i = s / NC, c = s % NC;
        int t = bid + i * GRID;
        size_t mB = (size_t)t * 128;
        const float* p = Af + (mB + crow) * KDIM + c * 32 + chalf * 16;
        *(float4*)(rA)      = *(const float4*)(p);
        *(float4*)(rA + 4)  = *(const float4*)(p + 4);
        *(float4*)(rA + 8)  = *(const float4*)(p + 8);
        *(float4*)(rA + 12) = *(const float4*)(p + 12);
    };
    auto storeA_regs = [&](uint32_t q) {
        uint32_t dst = sb + A_OFF + (q >> 1) * 16384 + crow * 128;
        uint32_t gb = 4u * (q & 1);
        uint32_t hh[8];
#pragma unroll
        for (int k = 0; k < 8; k++)
            hh[k] = packf2(rA[2 * k], rA[2 * k + 1]);
        STS128(dst + ((gb + 2 * chalf + 0) ^ cxor) * 16, hh[0], hh[1], hh[2], hh[3]);
        STS128(dst + ((gb + 2 * chalf + 1) ^ cxor) * 16, hh[4], hh[5], hh[6], hh[7]);
    };
    auto prefetch = [&](int ss) {
        if (ss < total) {
            int c = ss % NC;
            uint32_t q = (uint32_t)ss & 3;
            uint32_t gb = 4u * (q & 1);
            if (MODE == 1) {
                int i = ss / NC;
                int t = bid + i * GRID;
                size_t mB = (size_t)t * 128;
                const char* srcA = (const char*)(Ap + ((size_t)c * M_ROWS + mB + crow) * 32 + chalf * 16);
                uint32_t dstA = sb + A_OFF + (q >> 1) * 16384 + crow * 128;
#pragma unroll
                for (int j = 0; j < 2; j++)
                    CP16(dstA + ((gb + 2 * chalf + j) ^ cxor) * 16, srcA + j * 16);
            } else if (c >= RES_CH) {
                const int row = tid;
                const uint32_t rx = (uint32_t)(row & 7);
                const char* srcB = (const char*)(Wp + ((size_t)c * 256 + row) * 32);
                uint32_t dstB = sb + BS_OFF + (q >> 1) * 32768 + (uint32_t)row * 128;
#pragma unroll
                for (int j = 0; j < 4; j++)
                    CP16(dstB + ((gb + (uint32_t)j) ^ rx) * 16, srcB + j * 16);
            }
        }
        CPCOMMIT();
    };
    auto compute = [&](int sidx) {
        int c = sidx % NC;
        uint32_t q = (uint32_t)sidx & 3;
        uint32_t ga = 4u * (q & 1);
        uint32_t Ab = sb + A_OFF + (q >> 1) * 16384 + aRowOff;
        uint32_t Bb, gb;
        if (MODE == 0 && c >= RES_CH) {
            Bb = sb + BS_OFF + (q >> 1) * 32768 + bRowOff;
            gb = ga;
        } else {
            Bb = sb + (uint32_t)(c >> 1) * 32768 + bRowOff;
            gb = 4u * (uint32_t)(c & 1);
        }
#pragma unroll
        for (int ks = 0; ks < 2; ks++) {
            uint32_t bh[16];
#pragma unroll
            for (int nb = 0; nb < 4; nb++)
                ldsm4(Bb + (uint32_t)nb * 2048 + ((gb + 2 * ks + bKsel) ^ xr) * 16, bh + 4 * nb);
#pragma unroll
            for (int mi = 0; mi < 4; mi++) {
                uint32_t ah[4];
                ldsm4(Ab + mi * 2048 + ((ga + 2 * ks + aKsel) ^ xr) * 16, ah);
#pragma unroll
                for (int nj = 0; nj < 8; nj++)
                    mma_f16(acc[mi][nj], ah, bh[2 * nj], bh[2 * nj + 1]);
            }
        }
    };

    const int rloc = warp_m * 64 + (lane >> 2);
    const int nl0 = warp_n * 64 + (lane & 3) * 2;

    // ---- prologue ----
    prefetch(0);
    prefetch(1);
    if (MODE == 0) {
        loadA_regs(0); storeA_regs(0);
        if (total > 1) { loadA_regs(1); storeA_regs(1); }
        if (total > 2) loadA_regs(2);
    }

    // ---- main loop: ONE barrier per iteration ----
    for (int s = 0; s < total; s++) {
        prefetch(s + 2);
        CPWAIT2();
        __syncthreads();
        compute(s);

        if ((s % NC) == NC - 1) {
            const int t = bid + (s / NC) * GRID;
            const size_t mBase = (size_t)t * 128;
            if (MODE == 0) {
#pragma unroll
                for (int mi = 0; mi < 4; mi++)
#pragma unroll
                    for (int nj = 0; nj < 8; nj++) {
                        int nl = nl0 + nj * 8;
                        float b0v = biasS[nl], b1v = biasS[nl + 1];
                        float v00 = fmaxf(acc[mi][nj][0] + b0v, 0.f);
                        float v01 = fmaxf(acc[mi][nj][1] + b1v, 0.f);
                        float v10 = fmaxf(acc[mi][nj][2] + b0v, 0.f);
                        float v11 = fmaxf(acc[mi][nj][3] + b1v, 0.f);
                        int cpk = nl >> 5, slot = nl & 31;
                        size_t r0 = mBase + rloc + mi * 16;
                        size_t o0 = ((size_t)cpk * M_ROWS + r0) * 32 + slot;
                        size_t o1 = o0 + 8 * 32;
                        *(uint32_t*)(outp + o0) = packf2(v00, v01);
                        *(uint32_t*)(outp + o1) = packf2(v10, v11);
                        acc[mi][nj][0] = 0.f; acc[mi][nj][1] = 0.f;
                        acc[mi][nj][2] = 0.f; acc[mi][nj][3] = 0.f;
                    }
            } else {
                float up[16];
#pragma unroll
                for (int i = 0; i < 16; i++) up[i] = 0.f;
#pragma unroll
                for (int mi = 0; mi < 4; mi++)
#pragma unroll
                    for (int nj = 0; nj < 8; nj++) {
                        int nl = nl0 + nj * 8;
                        float b0v = biasS[nl], b1v = biasS[nl + 1];
                        float w00 = W2s[2 * nl],     w01 = W2s[2 * nl + 1];
                        float w10 = W2s[2 * nl + 2], w11 = W2s[2 * nl + 3];
                        float v00 = fmaxf(acc[mi][nj][0] + b0v, 0.f);
                        float v01 = fmaxf(acc[mi][nj][1] + b1v, 0.f);
                        float v10 = fmaxf(acc[mi][nj][2] + b0v, 0.f);
                        float v11 = fmaxf(acc[mi][nj][3] + b1v, 0.f);
                        up[mi * 4 + 0] += v00 * w00 + v01 * w10;
                        up[mi * 4 + 1] += v00 * w01 + v01 * w11;
                        up[mi * 4 + 2] += v10 * w00 + v11 * w10;
                        up[mi * 4 + 3] += v10 * w01 + v11 * w11;
                        acc[mi][nj][0] = 0.f; acc[mi][nj][1] = 0.f;
                        acc[mi][nj][2] = 0.f; acc[mi][nj][3] = 0.f;
                    }
#pragma unroll
                for (int k = 1; k <= 2; k <<= 1)
#pragma unroll
                    for (int i = 0; i < 16; i++)
                        up[i] += __shfl_xor_sync(0xffffffffu, up[i], k);

                // cross-warp_n reduction in smem, then plain stores (no atomics)
                float* sc = (float*)(smem + UN_SC);   // [3][128][2]
                if ((lane & 3) == 0 && warp_n > 0) {
#pragma unroll
                    for (int mi = 0; mi < 4; mi++) {
                        int r0l = rloc + mi * 16, r1l = r0l + 8;
                        sc[((warp_n - 1) * 128 + r0l) * 2 + 0] = up[mi * 4 + 0];
                        sc[((warp_n - 1) * 128 + r0l) * 2 + 1] = up[mi * 4 + 1];
                        sc[((warp_n - 1) * 128 + r1l) * 2 + 0] = up[mi * 4 + 2];
                        sc[((warp_n - 1) * 128 + r1l) * 2 + 1] = up[mi * 4 + 3];
                    }
                }
                __syncthreads();
                if (warp_n == 0 && (lane & 3) == 0) {
#pragma unroll
                    for (int mi = 0; mi < 4; mi++) {
                        int r0l = rloc + mi * 16, r1l = r0l + 8;
                        float s0 = up[mi * 4 + 0], s1 = up[mi * 4 + 1];
                        float s2 = up[mi * 4 + 2], s3 = up[mi * 4 + 3];
#pragma unroll
                        for (int w = 0; w < 3; w++) {
                            s0 += sc[(w * 128 + r0l) * 2 + 0];
                            s1 += sc[(w * 128 + r0l) * 2 + 1];
                            s2 += sc[(w * 128 + r1l) * 2 + 0];
                            s3 += sc[(w * 128 + r1l) * 2 + 1];
                        }
                        size_t r0 = mBase + r0l, r1 = mBase + r1l;
                        *(float2*)(un + r0 * 2) = make_float2(s0, s1);
                        *(float2*)(un + r1 * 2) = make_float2(s2, s3);
                    }
                }
            }
        }

        if (MODE == 0) {
            if (s + 2 < total) {
                storeA_regs((uint32_t)(s + 2) & 3);
                if (s + 3 < total) loadA_regs(s + 3);
            }
        }
    }
}

// ---------------- joint + lse + marginals -------------------------------------
__global__ __launch_bounds__(256) void joint_kernel(
    const float* __restrict__ un, const float* __restrict__ ps,
    const float* __restrict__ b2v, float* __restrict__ out_marg,
    float* __restrict__ out_joint)
{
    int w = blockIdx.x * 8 + (threadIdx.x >> 5);
    int lane = threadIdx.x & 31;
    int b = w & (BSZv - 1), n = w >> 9;
    size_t nb = (size_t)n * BSZv + b;

    float val = 0.f;
    if (lane < 14) val = un[nb * 14 + lane] + b2v[lane & 1];
    float u[14];
#pragma unroll
    for (int i = 0; i < 14; i++) u[i] = __shfl_sync(0xffffffffu, val, i);

    float j[4], e[4];
    float mx = -1e30f;
#pragma unroll
    for (int q = 0; q < 4; q++) {
        int s = q * 32 + lane;
        float t = ps[(size_t)b * NCFG + s];
#pragma unroll
        for (int i = 0; i < NE; i++) t += u[i * 2 + ((s >> (6 - i)) & 1)];
        j[q] = t;
        mx = fmaxf(mx, t);
    }
#pragma unroll
    for (int o = 16; o; o >>= 1) mx = fmaxf(mx, __shfl_xor_sync(0xffffffffu, mx, o));

    float p1[NE], p0[NE];
#pragma unroll
    for (int i = 0; i < NE; i++) { p1[i] = 0.f; p0[i] = 0.f; }
#pragma unroll
    for (int q = 0; q < 4; q++) {
        int s = q * 32 + lane;
        e[q] = __expf(j[q] - mx);
#pragma unroll
        for (int i = 0; i < NE; i++) {
            if ((s >> (6 - i)) & 1) p1[i] += e[q];
            else p0[i] += e[q];
        }
    }
#pragma unroll
    for (int o = 16; o; o >>= 1)
#pragma unroll
        for (int i = 0; i < NE; i++) {
            p1[i] += __shfl_xor_sync(0xffffffffu, p1[i], o);
            p0[i] += __shfl_xor_sync(0xffffffffu, p0[i], o);
        }

    float lt = __logf(p1[0] + p0[0]);
#pragma unroll
    for (int q = 0; q < 4; q++)
        out_joint[nb * NCFG + q * 32 + lane] = j[q] - mx - lt;
    if (lane < NE)
        out_marg[nb * NE + lane] = __logf(p1[lane]) - __logf(p0[lane]);
}

// ---------------- launch -------------------------------------------------------
extern "C" void kernel_launch(void* const* d_in, const int* in_sizes, int n_in,
                              void* d_out, int out_size)
{
    const float* input = (const float*)d_in[0];
    const float* ctx   = (const float*)d_in[1];
    const float* W0 = (const float*)d_in[4];
    const float* b0 = (const float*)d_in[5];
    const float* W1 = (const float*)d_in[6];
    const float* b1 = (const float*)d_in[7];
    const float* W2 = (const float*)d_in[8];
    const float* b2 = (const float*)d_in[9];
    const float* R0 = (const float*)d_in[10];
    const float* r0 = (const float*)d_in[11];
    const float* R1 = (const float*)d_in[12];
    const float* r1 = (const float*)d_in[13];

    float* out = (float*)d_out;
    float* out_marg = out;
    float* out_joint = out + (size_t)M_ROWS;

    __half *w0p, *w1p, *h1p;
    float *un, *psum;
    cudaGetSymbolAddress((void**)&w0p, g_w0p);
    cudaGetSymbolAddress((void**)&w1p, g_w1p);
    cudaGetSymbolAddress((void**)&h1p, g_h1p);
    cudaGetSymbolAddress((void**)&un, g_un);
    cudaGetSymbolAddress((void**)&psum, g_pairsum);

    cudaFuncSetAttribute(gemm_tc<DIN, 0>, cudaFuncAttributeMaxDynamicSharedMemorySize, SMEM_SZ0);
    cudaFuncSetAttribute(gemm_tc<DHv, 1>, cudaFuncAttributeMaxDynamicSharedMemorySize, SMEM_SZ1);

    prep_kernel<<<2048, 128>>>(ctx, R0, r0, R1, r1, psum, W0, w0p, W1, w1p);

    gemm_tc<DIN, 0><<<PGRID, 256, SMEM_SZ0>>>(
        input, nullptr, w0p, b0, nullptr, h1p, nullptr);
    gemm_tc<DHv, 1><<<PGRID, 256, SMEM_SZ1>>>(
        nullptr, h1p, w1p, b1, W2, nullptr, un);
    joint_kernel<<<(NN * BSZv) / 8, 256>>>(un, psum, b2, out_marg, out_joint);
}

// round 17
// speedup vs baseline: 1.3025x; 1.0482x over previous
#include <cuda_runtime.h>
#include <cuda_fp16.h>
#include <cstdint>
#include <math.h>

#define NN    32
#define BSZv  512
#define NE    7
#define DIN   512
#define DHv   256
#define RHv   64
#define NPAIR 21
#define M_ROWS (NN * BSZv * NE)   // 114688
#define NCFG  128
#define NTILES 896
#define PGRID  152

// ---------------- scratch ------------------------------------------------------
__device__ __align__(128) __half g_w0p[(size_t)(DIN / 32) * DHv * 32];
__device__ __align__(128) __half g_w1p[(size_t)(DHv / 32) * DHv * 32];
__device__ __align__(128) __half g_h1p[(size_t)(DHv / 32) * M_ROWS * 32];
__device__ float g_un[(size_t)M_ROWS * 2];
__device__ float g_pairsum[(size_t)BSZv * NCFG];

// ---------------- PTX helpers ---------------------------------------------------
__device__ __forceinline__ uint32_t smem_u32(const void* p) {
    uint32_t a;
    asm("{ .reg .u64 t; cvta.to.shared.u64 t, %1; cvt.u32.u64 %0, t; }" : "=r"(a) : "l"(p));
    return a;
}
__device__ __forceinline__ void ldsm4(uint32_t a, uint32_t* r) {
    asm volatile("ldmatrix.sync.aligned.m8n8.x4.shared.b16 {%0,%1,%2,%3}, [%4];"
                 : "=r"(r[0]), "=r"(r[1]), "=r"(r[2]), "=r"(r[3]) : "r"(a));
}
__device__ __forceinline__ void mma_f16(float* c, const uint32_t* a, uint32_t b0, uint32_t b1) {
    asm volatile("mma.sync.aligned.m16n8k16.row.col.f32.f16.f16.f32 "
                 "{%0,%1,%2,%3}, {%4,%5,%6,%7}, {%8,%9}, {%0,%1,%2,%3};"
                 : "+f"(c[0]), "+f"(c[1]), "+f"(c[2]), "+f"(c[3])
                 : "r"(a[0]), "r"(a[1]), "r"(a[2]), "r"(a[3]), "r"(b0), "r"(b1));
}
#define CP16(dst, src) asm volatile("cp.async.cg.shared.global [%0], [%1], 16;" :: "r"(dst), "l"(src))
#define CPCOMMIT()     asm volatile("cp.async.commit_group;" ::: "memory")
#define CPWAIT2()      asm volatile("cp.async.wait_group 2;" ::: "memory")
#define STS128(a, v0, v1, v2, v3) \
    asm volatile("st.shared.v4.b32 [%0], {%1,%2,%3,%4};" :: "r"(a), "r"(v0), "r"(v1), "r"(v2), "r"(v3))

__device__ __forceinline__ uint32_t packf2(float lo, float hi) {
    uint32_t d;
    asm("cvt.rn.f16x2.f32 %0, %1, %2;" : "=r"(d) : "f"(hi), "f"(lo));
    return d;
}

// ---------------- prep: binary MLP + pairsum, W0 pack, W1 pack (one launch) -----
__global__ __launch_bounds__(128) void prep_kernel(
    const float* __restrict__ ctx, const float* __restrict__ R0,
    const float* __restrict__ r0, const float* __restrict__ R1,
    const float* __restrict__ r1, float* __restrict__ pairsum,
    const float* __restrict__ W0, __half* __restrict__ w0p,
    const float* __restrict__ W1, __half* __restrict__ w1p)
{
    __shared__ float cd[NPAIR][5];
    __shared__ float R0s[5][RHv];
    __shared__ float r0s[RHv];
    __shared__ float R1s[RHv][3];
    __shared__ float r1s[3];
    __shared__ float h2s[NPAIR][RHv];
    __shared__ float bp4s[NPAIR][4];

    const int blk = blockIdx.x;
    const int t = threadIdx.x;

    if (blk >= 512) {
        if (blk < 1536) {
            int idx = (blk - 512) * 128 + t;
            int k = idx >> 8, n = idx & 255;
            size_t o = ((size_t)(k >> 5) * 256 + n) * 32 + (k & 31);
            w0p[o] = __float2half_rn(W0[idx]);
        } else {
            int idx = (blk - 1536) * 128 + t;
            int k = idx >> 8, n = idx & 255;
            size_t o = ((size_t)(k >> 5) * 256 + n) * 32 + (k & 31);
            w1p[o] = __float2half_rn(W1[idx]);
        }
        return;
    }

    const int b = blk;
    for (int i = t; i < NPAIR * 5; i += 128) cd[i / 5][i % 5] = ctx[b * NPAIR * 5 + i];
    for (int i = t; i < 5 * RHv; i += 128) R0s[i / RHv][i % RHv] = R0[i];
    if (t < RHv) r0s[t] = r0[t];
    for (int i = t; i < RHv * 3; i += 128) R1s[i / 3][i % 3] = R1[i];
    if (t < 3) r1s[t] = r1[t];
    __syncthreads();

    for (int idx = t; idx < NPAIR * RHv; idx += 128) {
        int p = idx / RHv, u = idx % RHv;
        float v = r0s[u];
#pragma unroll
        for (int x = 0; x < 5; x++) v += cd[p][x] * R0s[x][u];
        h2s[p][u] = fmaxf(v, 0.f);
    }
    __syncthreads();

    if (t < NPAIR * 3) {
        int p = t / 3, y = t % 3;
        float v = r1s[y];
#pragma unroll
        for (int u = 0; u < RHv; u++) v += h2s[p][u] * R1s[u][y];
        if (y == 0) bp4s[p][0] = v;
        else if (y == 1) { bp4s[p][1] = v; bp4s[p][2] = v; }
        else bp4s[p][3] = v;
    }
    __syncthreads();

    int s = t;
    float accv = 0.f;
    int p = 0;
#pragma unroll
    for (int i = 0; i < NE; i++)
#pragma unroll
        for (int j = i + 1; j < NE; j++) {
            int bi = (s >> (6 - i)) & 1;
            int bj = (s >> (6 - j)) & 1;
            accv += bp4s[p][bi * 2 + bj];
            p++;
        }
    pairsum[(size_t)b * NCFG + s] = accv;
}

// ---------------- GEMM: 128x256 CTA tile, 64x64 warp tile, 1 CTA/SM ------------
#define RES_SZ   131072u
#define A_OFF    131072u
#define BS_OFF   163840u
#define UN_SC    166912u
#define SMEM_SZ0 230400
#define SMEM_SZ1 169984

template <int KDIM, int MODE>
__global__ __launch_bounds__(256, 1) void gemm_tc(
    const float* __restrict__ Af, const __half* __restrict__ Ap,
    const __half* __restrict__ Wp, const float* __restrict__ bias,
    const float* __restrict__ W2, __half* __restrict__ outp,
    float* __restrict__ un)
{
    extern __shared__ char smem[];
    constexpr int NC = KDIM / 32;
    constexpr int RES_CH = 8;
    constexpr uint32_t SM_BIAS = (MODE == 0) ? 229376u : 163840u;
    constexpr uint32_t SM_W2v  = 164864u;
    const int tid = threadIdx.x;
    const int lane = tid & 31;
    const int wid = tid >> 5;
    const int warp_m = wid >> 2, warp_n = wid & 3;
    const int bid = blockIdx.x;
    const int GRID = gridDim.x;

    const uint32_t sb = smem_u32(smem);
    float* biasS = (float*)(smem + SM_BIAS);
    float* W2s = (float*)(smem + SM_W2v);
    biasS[tid] = bias[tid];
    if (MODE == 1) { W2s[tid] = W2[tid]; W2s[tid + 256] = W2[tid + 256]; }

    const int crow = tid >> 1;
    const int chalf = tid & 1;
    const int cxor = crow & 7;

    const uint32_t aRowOff = (uint32_t)(warp_m * 64 + (lane & 15)) * 128;
    const uint32_t aKsel = (uint32_t)(lane >> 4);
    const uint32_t bRowOff = (uint32_t)(warp_n * 64 + ((lane >> 4) << 3) + (lane & 7)) * 128;
    const uint32_t bKsel = (uint32_t)((lane >> 3) & 1);
    const uint32_t xr = (uint32_t)(lane & 7);

    const int myTiles = (NTILES - bid + GRID - 1) / GRID;
    const int total = myTiles * NC;

    float acc[4][8][4];
#pragma unroll
    for (int a = 0; a < 4; a++)
#pragma unroll
        for (int b = 0; b < 8; b++)
#pragma unroll
            for (int q = 0; q < 4; q++) acc[a][b][q] = 0.f;

    float rA[16];

    // ---- resident B ----
    {
        const int row = tid;
        const uint32_t rx = (uint32_t)(row & 7);
#pragma unroll
        for (int p = 0; p < RES_CH / 2; p++) {
#pragma unroll
            for (int e = 0; e < 2; e++) {
                const char* src = (const char*)(Wp + ((size_t)(2 * p + e) * 256 + row) * 32);
                uint32_t dst = sb + (uint32_t)p * 32768 + (uint32_t)row * 128;
#pragma unroll
                for (int j = 0; j < 4; j++)
                    CP16(dst + (((uint32_t)(4 * e + j)) ^ rx) * 16, src + j * 16);
            }
        }
        CPCOMMIT();
    }

    auto loadA_regs = [&](int s) {
        int i = s / NC, c = s % NC;
        int t = bid + i * GRID;
        size_t mB = (size_t)t * 128;
        const float* p = Af + (mB + crow) * KDIM + c * 32 + chalf * 16;
        *(float4*)(rA)      = *(const float4*)(p);
        *(float4*)(rA + 4)  = *(const float4*)(p + 4);
        *(float4*)(rA + 8)  = *(const float4*)(p + 8);
        *(float4*)(rA + 12) = *(const float4*)(p + 12);
    };
    auto storeA_regs = [&](uint32_t q) {
        uint32_t dst = sb + A_OFF + (q >> 1) * 16384 + crow * 128;
        uint32_t gb = 4u * (q & 1);
        uint32_t hh[8];
#pragma unroll
        for (int k = 0; k < 8; k++)
            hh[k] = packf2(rA[2 * k], rA[2 * k + 1]);
        STS128(dst + ((gb + 2 * chalf + 0) ^ cxor) * 16, hh[0], hh[1], hh[2], hh[3]);
        STS128(dst + ((gb + 2 * chalf + 1) ^ cxor) * 16, hh[4], hh[5], hh[6], hh[7]);
    };
    auto prefetch = [&](int ss) {
        if (ss < total) {
            int c = ss % NC;
            uint32_t q = (uint32_t)ss & 3;
            uint32_t gb = 4u * (q & 1);
            if (MODE == 1) {
                int i = ss / NC;
                int t = bid + i * GRID;
                size_t mB = (size_t)t * 128;
                const char* srcA = (const char*)(Ap + ((size_t)c * M_ROWS + mB + crow) * 32 + chalf * 16);
                uint32_t dstA = sb + A_OFF + (q >> 1) * 16384 + crow * 128;
#pragma unroll
                for (int j = 0; j < 2; j++)
                    CP16(dstA + ((gb + 2 * chalf + j) ^ cxor) * 16, srcA + j * 16);
            } else if (c >= RES_CH) {
                const int row = tid;
                const uint32_t rx = (uint32_t)(row & 7);
                const char* srcB = (const char*)(Wp + ((size_t)c * 256 + row) * 32);
                uint32_t dstB = sb + BS_OFF + (q >> 1) * 32768 + (uint32_t)row * 128;
#pragma unroll
                for (int j = 0; j < 4; j++)
                    CP16(dstB + ((gb + (uint32_t)j) ^ rx) * 16, srcB + j * 16);
            }
        }
        CPCOMMIT();
    };
    auto compute = [&](int sidx) {
        int c = sidx % NC;
        uint32_t q = (uint32_t)sidx & 3;
        uint32_t ga = 4u * (q & 1);
        uint32_t Ab = sb + A_OFF + (q >> 1) * 16384 + aRowOff;
        uint32_t Bb, gb;
        if (MODE == 0 && c >= RES_CH) {
            Bb = sb + BS_OFF + (q >> 1) * 32768 + bRowOff;
            gb = ga;
        } else {
            Bb = sb + (uint32_t)(c >> 1) * 32768 + bRowOff;
            gb = 4u * (uint32_t)(c & 1);
        }
#pragma unroll
        for (int ks = 0; ks < 2; ks++) {
            uint32_t bh[16];
#pragma unroll
            for (int nb = 0; nb < 4; nb++)
                ldsm4(Bb + (uint32_t)nb * 2048 + ((gb + 2 * ks + bKsel) ^ xr) * 16, bh + 4 * nb);
#pragma unroll
            for (int mi = 0; mi < 4; mi++) {
                uint32_t ah[4];
                ldsm4(Ab + mi * 2048 + ((ga + 2 * ks + aKsel) ^ xr) * 16, ah);
#pragma unroll
                for (int nj = 0; nj < 8; nj++)
                    mma_f16(acc[mi][nj], ah, bh[2 * nj], bh[2 * nj + 1]);
            }
        }
    };

    const int rloc = warp_m * 64 + (lane >> 2);
    const int nl0 = warp_n * 64 + (lane & 3) * 2;

    // ---- prologue ----
    prefetch(0);
    prefetch(1);
    if (MODE == 0) {
        loadA_regs(0); storeA_regs(0);
        if (total > 1) { loadA_regs(1); storeA_regs(1); }
        if (total > 2) loadA_regs(2);
    }

    // ---- main loop: ONE barrier per iteration ----
    for (int s = 0; s < total; s++) {
        prefetch(s + 2);
        CPWAIT2();
        __syncthreads();
        compute(s);

        if ((s % NC) == NC - 1) {
            const int t = bid + (s / NC) * GRID;
            const size_t mBase = (size_t)t * 128;
            if (MODE == 0) {
#pragma unroll
                for (int mi = 0; mi < 4; mi++)
#pragma unroll
                    for (int nj = 0; nj < 8; nj++) {
                        int nl = nl0 + nj * 8;
                        float b0v = biasS[nl], b1v = biasS[nl + 1];
                        float v00 = fmaxf(acc[mi][nj][0] + b0v, 0.f);
                        float v01 = fmaxf(acc[mi][nj][1] + b1v, 0.f);
                        float v10 = fmaxf(acc[mi][nj][2] + b0v, 0.f);
                        float v11 = fmaxf(acc[mi][nj][3] + b1v, 0.f);
                        int cpk = nl >> 5, slot = nl & 31;
                        size_t r0 = mBase + rloc + mi * 16;
                        size_t o0 = ((size_t)cpk * M_ROWS + r0) * 32 + slot;
                        size_t o1 = o0 + 8 * 32;
                        *(uint32_t*)(outp + o0) = packf2(v00, v01);
                        *(uint32_t*)(outp + o1) = packf2(v10, v11);
                        acc[mi][nj][0] = 0.f; acc[mi][nj][1] = 0.f;
                        acc[mi][nj][2] = 0.f; acc[mi][nj][3] = 0.f;
                    }
            } else {
                float up[16];
#pragma unroll
                for (int i = 0; i < 16; i++) up[i] = 0.f;
#pragma unroll
                for (int mi = 0; mi < 4; mi++)
#pragma unroll
                    for (int nj = 0; nj < 8; nj++) {
                        int nl = nl0 + nj * 8;
                        float b0v = biasS[nl], b1v = biasS[nl + 1];
                        float w00 = W2s[2 * nl],     w01 = W2s[2 * nl + 1];
                        float w10 = W2s[2 * nl + 2], w11 = W2s[2 * nl + 3];
                        float v00 = fmaxf(acc[mi][nj][0] + b0v, 0.f);
                        float v01 = fmaxf(acc[mi][nj][1] + b1v, 0.f);
                        float v10 = fmaxf(acc[mi][nj][2] + b0v, 0.f);
                        float v11 = fmaxf(acc[mi][nj][3] + b1v, 0.f);
                        up[mi * 4 + 0] += v00 * w00 + v01 * w10;
                        up[mi * 4 + 1] += v00 * w01 + v01 * w11;
                        up[mi * 4 + 2] += v10 * w00 + v11 * w10;
                        up[mi * 4 + 3] += v10 * w01 + v11 * w11;
                        acc[mi][nj][0] = 0.f; acc[mi][nj][1] = 0.f;
                        acc[mi][nj][2] = 0.f; acc[mi][nj][3] = 0.f;
                    }
#pragma unroll
                for (int k = 1; k <= 2; k <<= 1)
#pragma unroll
                    for (int i = 0; i < 16; i++)
                        up[i] += __shfl_xor_sync(0xffffffffu, up[i], k);

                float* sc = (float*)(smem + UN_SC);
                if ((lane & 3) == 0 && warp_n > 0) {
#pragma unroll
                    for (int mi = 0; mi < 4; mi++) {
                        int r0l = rloc + mi * 16, r1l = r0l + 8;
                        sc[((warp_n - 1) * 128 + r0l) * 2 + 0] = up[mi * 4 + 0];
                        sc[((warp_n - 1) * 128 + r0l) * 2 + 1] = up[mi * 4 + 1];
                        sc[((warp_n - 1) * 128 + r1l) * 2 + 0] = up[mi * 4 + 2];
                        sc[((warp_n - 1) * 128 + r1l) * 2 + 1] = up[mi * 4 + 3];
                    }
                }
                __syncthreads();
                if (warp_n == 0 && (lane & 3) == 0) {
#pragma unroll
                    for (int mi = 0; mi < 4; mi++) {
                        int r0l = rloc + mi * 16, r1l = r0l + 8;
                        float s0 = up[mi * 4 + 0], s1 = up[mi * 4 + 1];
                        float s2 = up[mi * 4 + 2], s3 = up[mi * 4 + 3];
#pragma unroll
                        for (int w = 0; w < 3; w++) {
                            s0 += sc[(w * 128 + r0l) * 2 + 0];
                            s1 += sc[(w * 128 + r0l) * 2 + 1];
                            s2 += sc[(w * 128 + r1l) * 2 + 0];
                            s3 += sc[(w * 128 + r1l) * 2 + 1];
                        }
                        size_t r0 = mBase + r0l, r1 = mBase + r1l;
                        *(float2*)(un + r0 * 2) = make_float2(s0, s1);
                        *(float2*)(un + r1 * 2) = make_float2(s2, s3);
                    }
                }
            }
        }

        if (MODE == 0) {
            if (s + 2 < total) {
                storeA_regs((uint32_t)(s + 2) & 3);
                if (s + 3 < total) loadA_regs(s + 3);
            }
        }
    }
}

// ---------------- joint + lse + marginals (optimized reductions) ----------------
__global__ __launch_bounds__(256) void joint_kernel(
    const float* __restrict__ un, const float* __restrict__ ps,
    const float* __restrict__ b2v, float* __restrict__ out_marg,
    float* __restrict__ out_joint)
{
    const uint32_t FULL = 0xffffffffu;
    int w = blockIdx.x * 8 + (threadIdx.x >> 5);
    int lane = threadIdx.x & 31;
    int b = w & (BSZv - 1), n = w >> 9;
    size_t nb = (size_t)n * BSZv + b;

    float val = 0.f;
    if (lane < 14) val = un[nb * 14 + lane] + b2v[lane & 1];
    float u[14];
#pragma unroll
    for (int i = 0; i < 14; i++) u[i] = __shfl_sync(FULL, val, i);

    float j[4];
    float mx = -1e30f;
#pragma unroll
    for (int q = 0; q < 4; q++) {
        int s = q * 32 + lane;
        float t = ps[(size_t)b * NCFG + s];
#pragma unroll
        for (int i = 0; i < NE; i++) t += u[i * 2 + ((s >> (6 - i)) & 1)];
        j[q] = t;
        mx = fmaxf(mx, t);
    }
#pragma unroll
    for (int o = 16; o; o >>= 1) mx = fmaxf(mx, __shfl_xor_sync(FULL, mx, o));

    float e0 = __expf(j[0] - mx);
    float e1 = __expf(j[1] - mx);
    float e2 = __expf(j[2] - mx);
    float e3 = __expf(j[3] - mx);

    // q-combination sums: A={q0,q1}, B={q2,q3}, C={q1,q3}, D={q0,q2}
    float A = e0 + e1, B = e2 + e3, C = e1 + e3, D = e0 + e2;
    float f = A + B;                       // lane-local total (before butterfly)
#pragma unroll
    for (int o = 16; o; o >>= 1) {
        A += __shfl_xor_sync(FULL, A, o);
        B += __shfl_xor_sync(FULL, B, o);
        C += __shfl_xor_sync(FULL, C, o);
        D += __shfl_xor_sync(FULL, D, o);
    }
    float tot = A + B;
    float lt = __logf(tot);

    // out_joint stores (coalesced per q)
#pragma unroll
    for (int q = 0; q < 4; q++)
        out_joint[nb * NCFG + q * 32 + lane] = j[q] - mx - lt;

    // entities 2..6: leave-one-bit-out butterflies on f (exact p0 & p1)
    float p1e[5], p0e[5];                  // index d: entity 2+d, lane bit kb=4-d
#pragma unroll
    for (int d = 0; d < 5; d++) {
        const int kb = 4 - d;
        const int ko = 1 << kb;
        float g = f;
#pragma unroll
        for (int o = 16; o; o >>= 1)
            if (o != ko) g += __shfl_xor_sync(FULL, g, o);
        float go = __shfl_xor_sync(FULL, g, ko);
        bool mybit = (lane >> kb) & 1;
        p1e[d] = mybit ? g : go;
        p0e[d] = mybit ? go : g;
    }

    // marginal logs: warp-uniform, computed on lane 0 only
    if (lane == 0) {
        float* om = out_marg + nb * NE;
        om[0] = __logf(B) - __logf(A);     // entity 0: bit6 = q>>1
        om[1] = __logf(C) - __logf(D);     // entity 1: bit5 = q&1
#pragma unroll
        for (int d = 0; d < 5; d++)
            om[2 + d] = __logf(p1e[d]) - __logf(p0e[d]);
    }
}

// ---------------- launch -------------------------------------------------------
extern "C" void kernel_launch(void* const* d_in, const int* in_sizes, int n_in,
                              void* d_out, int out_size)
{
    const float* input = (const float*)d_in[0];
    const float* ctx   = (const float*)d_in[1];
    const float* W0 = (const float*)d_in[4];
    const float* b0 = (const float*)d_in[5];
    const float* W1 = (const float*)d_in[6];
    const float* b1 = (const float*)d_in[7];
    const float* W2 = (const float*)d_in[8];
    const float* b2 = (const float*)d_in[9];
    const float* R0 = (const float*)d_in[10];
    const float* r0 = (const float*)d_in[11];
    const float* R1 = (const float*)d_in[12];
    const float* r1 = (const float*)d_in[13];

    float* out = (float*)d_out;
    float* out_marg = out;
    float* out_joint = out + (size_t)M_ROWS;

    __half *w0p, *w1p, *h1p;
    float *un, *psum;
    cudaGetSymbolAddress((void**)&w0p, g_w0p);
    cudaGetSymbolAddress((void**)&w1p, g_w1p);
    cudaGetSymbolAddress((void**)&h1p, g_h1p);
    cudaGetSymbolAddress((void**)&un, g_un);
    cudaGetSymbolAddress((void**)&psum, g_pairsum);

    cudaFuncSetAttribute(gemm_tc<DIN, 0>, cudaFuncAttributeMaxDynamicSharedMemorySize, SMEM_SZ0);
    cudaFuncSetAttribute(gemm_tc<DHv, 1>, cudaFuncAttributeMaxDynamicSharedMemorySize, SMEM_SZ1);

    prep_kernel<<<2048, 128>>>(ctx, R0, r0, R1, r1, psum, W0, w0p, W1, w1p);

    gemm_tc<DIN, 0><<<PGRID, 256, SMEM_SZ0>>>(
        input, nullptr, w0p, b0, nullptr, h1p, nullptr);
    gemm_tc<DHv, 1><<<PGRID, 256, SMEM_SZ1>>>(
        nullptr, h1p, w1p, b1, W2, nullptr, un);
    joint_kernel<<<(NN * BSZv) / 8, 256>>>(un, psum, b2, out_marg, out_joint);
}